// round 6
// baseline (speedup 1.0000x reference)
#include <cuda_runtime.h>
#include <cuda_fp16.h>

#define B_ 16
#define N_ 512
#define H_ 8
#define D_ 64
#define BM 128
#define BN 64
#define NTILES 8
// C2 = 8*log2(e): base-2 logit scale (sqrt(D)=8 folded); C4 = 2*C2 pre-applied to Q
#define C2 11.541560327111707f
#define C4 23.083120654223414f

// smem layout: QLO (static 16KB) + two K/V stages
#define QLO_OFF 0
#define STAGE0 16384
// within a stage:
#define KHI 0
#define KLO 8192
#define VHI 16384
#define K2C 24576
#define STG 24832
#define SMEM_BYTES (STAGE0 + 2*STG)

typedef unsigned int u32;

__device__ __forceinline__ u32 swz(u32 x){ return x ^ ((x >> 3) & 0x70u); }

__device__ __forceinline__ u32 s2u(const void* p){
  u32 a; asm("{ .reg .u64 t; cvta.to.shared.u64 t, %1; cvt.u32.u64 %0, t; }" : "=r"(a) : "l"(p));
  return a;
}
__device__ __forceinline__ float ex2(float x){
  float r; asm("ex2.approx.f32 %0, %1;" : "=f"(r) : "f"(x)); return r;
}
__device__ __forceinline__ u32 packsplit(float a, float b, u32& lo){
  __half ha = __float2half_rn(a), hb = __float2half_rn(b);
  __half la = __float2half_rn(a - __half2float(ha));
  __half lb = __float2half_rn(b - __half2float(hb));
  lo = (u32)__half_as_ushort(la) | ((u32)__half_as_ushort(lb) << 16);
  return (u32)__half_as_ushort(ha) | ((u32)__half_as_ushort(hb) << 16);
}
__device__ __forceinline__ u32 packh(float a, float b){
  __half ha = __float2half_rn(a), hb = __float2half_rn(b);
  return (u32)__half_as_ushort(ha) | ((u32)__half_as_ushort(hb) << 16);
}
__device__ __forceinline__ void mma16816(float* c, u32 a0, u32 a1, u32 a2, u32 a3,
                                         u32 b0, u32 b1){
  asm volatile(
    "mma.sync.aligned.m16n8k16.row.col.f32.f16.f16.f32 "
    "{%0,%1,%2,%3}, {%4,%5,%6,%7}, {%8,%9}, {%0,%1,%2,%3};"
    : "+f"(c[0]), "+f"(c[1]), "+f"(c[2]), "+f"(c[3])
    : "r"(a0), "r"(a1), "r"(a2), "r"(a3), "r"(b0), "r"(b1));
}
__device__ __forceinline__ void ldm4(u32 addr, u32& r0, u32& r1, u32& r2, u32& r3){
  asm volatile("ldmatrix.sync.aligned.m8n8.x4.shared.b16 {%0,%1,%2,%3}, [%4];"
    : "=r"(r0), "=r"(r1), "=r"(r2), "=r"(r3) : "r"(addr));
}
__device__ __forceinline__ void ldm4t(u32 addr, u32& r0, u32& r1, u32& r2, u32& r3){
  asm volatile("ldmatrix.sync.aligned.m8n8.x4.trans.shared.b16 {%0,%1,%2,%3}, [%4];"
    : "=r"(r0), "=r"(r1), "=r"(r2), "=r"(r3) : "r"(addr));
}

__global__ void __launch_bounds__(256, 2) geo_attn_mma(
    const float* __restrict__ q, const float* __restrict__ k,
    const float* __restrict__ v, const float* __restrict__ geo,
    float* __restrict__ out)
{
  extern __shared__ __align__(128) char smc[];
  const u32 smb = s2u(smc);
  const int tid = threadIdx.x, w = tid >> 5, l = tid & 31;
  const int qr = l >> 2;
  const int qc = l & 3;
  const int r0 = w * 16 + qr;
  const int qt = blockIdx.x, h = blockIdx.y, b = blockIdx.z;
  const int n0 = qt * BM;
  const int rowstride = H_ * D_;

  // B-operand ldmatrix lane address bases
  const u32 kfrag = (u32)((l & 7) * 128 + (l >> 3) * 16);
  const u32 vfrag = (u32)(((l >> 3) & 1) * 1024 + (l & 7) * 128 + (l >> 4) * 16);
  // A-operand (Q_lo) ldmatrix lane base: m=l>>3 -> row (m&1)*8+(l&7), halfcol (m>>1)
  const u32 qlbase = (u32)((w*16 + ((l >> 3) & 1)*8 + (l & 7))*128 + (l >> 4)*16);

  const float* kb = k + ((size_t)b*N_*H_ + h)*D_;
  const float* vb = v + ((size_t)b*N_*H_ + h)*D_;

  // per-thread K/V tile load indices (4 threads per key row)
  const int lr = tid >> 2, lc = tid & 3, ld0 = lc * 16;
  const u32 lo0 = swz((u32)(lr*128 + ld0*2));
  const u32 lo1 = swz((u32)(lr*128 + ld0*2 + 16));

  // ---- write Q_lo tile to smem (2 threads per row, 32 cols each) ----
  {
    const int rq = tid >> 1, cq = (tid & 1) * 32;
    const float* qsrc = q + ((size_t)(b*N_ + n0 + rq)*H_ + h)*D_ + cq;
    u32 lop[16];
    #pragma unroll
    for (int c = 0; c < 8; c++){
      float4 x = *(const float4*)(qsrc + c*4);
      u32 dummy_lo0, dummy_lo1;
      u32 h0 = packsplit(C4*x.x, C4*x.y, dummy_lo0); (void)h0;
      u32 h1 = packsplit(C4*x.z, C4*x.w, dummy_lo1); (void)h1;
      lop[c*2] = dummy_lo0; lop[c*2+1] = dummy_lo1;
    }
    const u32 base = (u32)(rq*128 + cq*2);
    #pragma unroll
    for (int c = 0; c < 4; c++){
      *(uint4*)(smc + QLO_OFF + swz(base + c*16)) =
        make_uint4(lop[c*4], lop[c*4+1], lop[c*4+2], lop[c*4+3]);
    }
  }

  // ---- Q_hi A-fragments from global, pre-scaled by 2*C2 ----
  u32 aqh[4][4];
  {
    const float* qb = q + ((size_t)(b*N_ + n0 + r0)*H_ + h)*D_;
    #pragma unroll
    for (int ks = 0; ks < 4; ks++){
      const int c0 = ks*16 + qc*2;
      float2 x00 = *(const float2*)(qb + c0);
      float2 x10 = *(const float2*)(qb + 8*rowstride + c0);
      float2 x01 = *(const float2*)(qb + c0 + 8);
      float2 x11 = *(const float2*)(qb + 8*rowstride + c0 + 8);
      aqh[ks][0] = packh(C4*x00.x, C4*x00.y);
      aqh[ks][1] = packh(C4*x10.x, C4*x10.y);
      aqh[ks][2] = packh(C4*x01.x, C4*x01.y);
      aqh[ks][3] = packh(C4*x11.x, C4*x11.y);
    }
  }

  float oacc[NTILES][4];
  #pragma unroll
  for (int t = 0; t < NTILES; t++){
    oacc[t][0]=0.f; oacc[t][1]=0.f; oacc[t][2]=0.f; oacc[t][3]=0.f;
  }
  float mold0 = -1e30f, mold1 = -1e30f, ls0 = 0.f, ls1 = 0.f;

  const float* grow = geo + (size_t)b*(N_*N_) + (size_t)(n0 + r0)*N_ + qc*2;

  // ---- prologue: tile 0 into stage 0 ----
  {
    const float* ksrc = kb + (size_t)lr*rowstride + ld0;
    const float* vsrc = vb + (size_t)lr*rowstride + ld0;
    float4 kreg[4], vreg[4];
    #pragma unroll
    for (int c = 0; c < 4; c++){ kreg[c] = *(const float4*)(ksrc + c*4); }
    #pragma unroll
    for (int c = 0; c < 4; c++){ vreg[c] = *(const float4*)(vsrc + c*4); }
    float k2p = 0.f;
    u32 hp[8], lp[8];
    #pragma unroll
    for (int c = 0; c < 4; c++){
      float4 x = kreg[c];
      k2p += x.x*x.x + x.y*x.y + x.z*x.z + x.w*x.w;
      hp[c*2]   = packsplit(x.x, x.y, lp[c*2]);
      hp[c*2+1] = packsplit(x.z, x.w, lp[c*2+1]);
    }
    *(uint4*)(smc + STAGE0 + KHI + lo0) = make_uint4(hp[0], hp[1], hp[2], hp[3]);
    *(uint4*)(smc + STAGE0 + KHI + lo1) = make_uint4(hp[4], hp[5], hp[6], hp[7]);
    *(uint4*)(smc + STAGE0 + KLO + lo0) = make_uint4(lp[0], lp[1], lp[2], lp[3]);
    *(uint4*)(smc + STAGE0 + KLO + lo1) = make_uint4(lp[4], lp[5], lp[6], lp[7]);
    k2p += __shfl_xor_sync(0xffffffffu, k2p, 1);
    k2p += __shfl_xor_sync(0xffffffffu, k2p, 2);
    if (lc == 0) ((float*)(smc + STAGE0 + K2C))[lr] = C2 * k2p;
    u32 vp[8];
    #pragma unroll
    for (int c = 0; c < 4; c++){
      float4 x = vreg[c];
      vp[c*2]   = packh(x.x, x.y);
      vp[c*2+1] = packh(x.z, x.w);
    }
    *(uint4*)(smc + STAGE0 + VHI + lo0) = make_uint4(vp[0], vp[1], vp[2], vp[3]);
    *(uint4*)(smc + STAGE0 + VHI + lo1) = make_uint4(vp[4], vp[5], vp[6], vp[7]);
  }
  __syncthreads();

  for (int mt = 0; mt < NTILES; mt++){
    const int m0 = mt * BN;
    const u32 st  = STAGE0 + (u32)(mt & 1) * STG;
    const u32 stn = STAGE0 + (u32)((mt+1) & 1) * STG;

    // ---- issue K(t+1) LDGs (consumed after the QK MMA block) ----
    float4 kreg[4];
    if (mt < NTILES-1){
      const float* ksrc = kb + (size_t)(m0 + BN + lr)*rowstride + ld0;
      #pragma unroll
      for (int c = 0; c < 4; c++) kreg[c] = *(const float4*)(ksrc + c*4);
    }

    // ---- S = Q @ K^T (3-term fp16 split; ql from smem) ----
    float sacc[NTILES][4];
    #pragma unroll
    for (int t = 0; t < NTILES; t++){
      sacc[t][0]=0.f; sacc[t][1]=0.f; sacc[t][2]=0.f; sacc[t][3]=0.f;
    }
    #pragma unroll
    for (int ks2 = 0; ks2 < 2; ks2++){
      const int ka = 2*ks2, kb2 = 2*ks2 + 1;
      u32 qa0,qa1,qa2,qa3, qb0,qb1,qb2,qb3;
      ldm4(smb + QLO_OFF + swz(qlbase + (u32)ka*32), qa0, qa1, qa2, qa3);
      ldm4(smb + QLO_OFF + swz(qlbase + (u32)kb2*32), qb0, qb1, qb2, qb3);
      #pragma unroll
      for (int nt = 0; nt < NTILES; nt++){
        const u32 off = swz(kfrag + (u32)(nt*1024 + ks2*64));
        u32 h0,h1,h2,h3, l0,l1,l2,l3;
        ldm4(smb + st + KHI + off, h0, h1, h2, h3);
        ldm4(smb + st + KLO + off, l0, l1, l2, l3);
        mma16816(sacc[nt], aqh[ka][0], aqh[ka][1], aqh[ka][2], aqh[ka][3], h0, h1);
        mma16816(sacc[nt], aqh[ka][0], aqh[ka][1], aqh[ka][2], aqh[ka][3], l0, l1);
        mma16816(sacc[nt], qa0, qa1, qa2, qa3, h0, h1);
        mma16816(sacc[nt], aqh[kb2][0], aqh[kb2][1], aqh[kb2][2], aqh[kb2][3], h2, h3);
        mma16816(sacc[nt], aqh[kb2][0], aqh[kb2][1], aqh[kb2][2], aqh[kb2][3], l2, l3);
        mma16816(sacc[nt], qb0, qb1, qb2, qb3, h2, h3);
      }
    }

    // ---- convert + STS K(t+1); then issue V(t+1) LDGs ----
    float4 vreg[4];
    if (mt < NTILES-1){
      float k2p = 0.f;
      u32 hp[8], lp[8];
      #pragma unroll
      for (int c = 0; c < 4; c++){
        float4 x = kreg[c];
        k2p += x.x*x.x + x.y*x.y + x.z*x.z + x.w*x.w;
        hp[c*2]   = packsplit(x.x, x.y, lp[c*2]);
        hp[c*2+1] = packsplit(x.z, x.w, lp[c*2+1]);
      }
      *(uint4*)(smc + stn + KHI + lo0) = make_uint4(hp[0], hp[1], hp[2], hp[3]);
      *(uint4*)(smc + stn + KHI + lo1) = make_uint4(hp[4], hp[5], hp[6], hp[7]);
      *(uint4*)(smc + stn + KLO + lo0) = make_uint4(lp[0], lp[1], lp[2], lp[3]);
      *(uint4*)(smc + stn + KLO + lo1) = make_uint4(lp[4], lp[5], lp[6], lp[7]);
      k2p += __shfl_xor_sync(0xffffffffu, k2p, 1);
      k2p += __shfl_xor_sync(0xffffffffu, k2p, 2);
      if (lc == 0) ((float*)(smc + stn + K2C))[lr] = C2 * k2p;
      const float* vsrc = vb + (size_t)(m0 + BN + lr)*rowstride + ld0;
      #pragma unroll
      for (int c = 0; c < 4; c++) vreg[c] = *(const float4*)(vsrc + c*4);
    }

    // ---- logits + online softmax ----
    float mx0 = -1e30f, mx1 = -1e30f;
    #pragma unroll
    for (int nt = 0; nt < NTILES; nt++){
      const float2 kk = *(const float2*)((const float*)(smc + st + K2C) + nt*8 + qc*2);
      const float2 g0 = *(const float2*)(grow + m0 + nt*8);
      const float2 g1 = *(const float2*)(grow + 8*N_ + m0 + nt*8);
      float t00 = fmaf(C2, g0.x, sacc[nt][0] - kk.x);
      float t01 = fmaf(C2, g0.y, sacc[nt][1] - kk.y);
      float t10 = fmaf(C2, g1.x, sacc[nt][2] - kk.x);
      float t11 = fmaf(C2, g1.y, sacc[nt][3] - kk.y);
      sacc[nt][0]=t00; sacc[nt][1]=t01; sacc[nt][2]=t10; sacc[nt][3]=t11;
      mx0 = fmaxf(mx0, fmaxf(t00, t01));
      mx1 = fmaxf(mx1, fmaxf(t10, t11));
    }
    #pragma unroll
    for (int d = 1; d < 4; d <<= 1){
      mx0 = fmaxf(mx0, __shfl_xor_sync(0xffffffffu, mx0, d));
      mx1 = fmaxf(mx1, __shfl_xor_sync(0xffffffffu, mx1, d));
    }
    const float mnew0 = fmaxf(mold0, mx0), mnew1 = fmaxf(mold1, mx1);
    const float al0 = ex2(mold0 - mnew0), al1 = ex2(mold1 - mnew1);
    mold0 = mnew0; mold1 = mnew1;
    float ps0 = 0.f, ps1 = 0.f;
    #pragma unroll
    for (int nt = 0; nt < NTILES; nt++){
      float p0 = ex2(sacc[nt][0] - mnew0);
      float p1 = ex2(sacc[nt][1] - mnew0);
      float p2 = ex2(sacc[nt][2] - mnew1);
      float p3 = ex2(sacc[nt][3] - mnew1);
      sacc[nt][0]=p0; sacc[nt][1]=p1; sacc[nt][2]=p2; sacc[nt][3]=p3;
      ps0 += p0 + p1; ps1 += p2 + p3;
    }
    #pragma unroll
    for (int d = 1; d < 4; d <<= 1){
      ps0 += __shfl_xor_sync(0xffffffffu, ps0, d);
      ps1 += __shfl_xor_sync(0xffffffffu, ps1, d);
    }
    ls0 = ls0*al0 + ps0;
    ls1 = ls1*al1 + ps1;
    #pragma unroll
    for (int t = 0; t < NTILES; t++){
      oacc[t][0]*=al0; oacc[t][1]*=al0; oacc[t][2]*=al1; oacc[t][3]*=al1;
    }

    // ---- convert + STS V(t+1) (stage stn; PV below reads stage st) ----
    if (mt < NTILES-1){
      u32 vp[8];
      #pragma unroll
      for (int c = 0; c < 4; c++){
        float4 x = vreg[c];
        vp[c*2]   = packh(x.x, x.y);
        vp[c*2+1] = packh(x.z, x.w);
      }
      *(uint4*)(smc + stn + VHI + lo0) = make_uint4(vp[0], vp[1], vp[2], vp[3]);
      *(uint4*)(smc + stn + VHI + lo1) = make_uint4(vp[4], vp[5], vp[6], vp[7]);
    }

    // ---- O += P @ V ----
    #pragma unroll
    for (int ks = 0; ks < 4; ks++){
      const u32 a0 = packh(sacc[2*ks][0],   sacc[2*ks][1]);
      const u32 a1 = packh(sacc[2*ks][2],   sacc[2*ks][3]);
      const u32 a2 = packh(sacc[2*ks+1][0], sacc[2*ks+1][1]);
      const u32 a3 = packh(sacc[2*ks+1][2], sacc[2*ks+1][3]);
      #pragma unroll
      for (int dt2 = 0; dt2 < 4; dt2++){
        const u32 off = swz(vfrag + (u32)(ks*2048 + dt2*32));
        u32 h0,h1,h2,h3;
        ldm4t(smb + st + VHI + off, h0, h1, h2, h3);
        mma16816(oacc[2*dt2],   a0, a1, a2, a3, h0, h1);
        mma16816(oacc[2*dt2+1], a0, a1, a2, a3, h2, h3);
      }
    }

    __syncthreads();   // stage reads done; next iter may overwrite
  }

  // ---- epilogue ----
  {
    const float inv0 = 1.f / ls0, inv1 = 1.f / ls1;
    float* ob = out + ((size_t)(b*N_ + n0 + r0)*H_ + h)*D_ + qc*2;
    #pragma unroll
    for (int dt = 0; dt < NTILES; dt++){
      float2 r4a; r4a.x = oacc[dt][0]*inv0; r4a.y = oacc[dt][1]*inv0;
      float2 r4b; r4b.x = oacc[dt][2]*inv1; r4b.y = oacc[dt][3]*inv1;
      *(float2*)(ob + dt*8) = r4a;
      *(float2*)(ob + 8*rowstride + dt*8) = r4b;
    }
  }
}

extern "C" void kernel_launch(void* const* d_in, const int* in_sizes, int n_in,
                              void* d_out, int out_size) {
  const float* q = (const float*)d_in[0];
  const float* k = (const float*)d_in[1];
  const float* v = (const float*)d_in[2];
  const float* g = (const float*)d_in[3];
  float* out = (float*)d_out;

  cudaFuncSetAttribute(geo_attn_mma, cudaFuncAttributeMaxDynamicSharedMemorySize, SMEM_BYTES);
  dim3 grid(N_/BM, H_, B_);
  geo_attn_mma<<<grid, 256, SMEM_BYTES>>>(q, k, v, g, out);
}